// round 16
// baseline (speedup 1.0000x reference)
#include <cuda_runtime.h>

#define BATCH 32
#define CH    512
#define HH    64
#define WW    64
#define KSEL  256           // RATIO 0.5 * 512
#define PLANE (HH * WW)     // 4096

// Scratch (allocation-free rule: __device__ globals)
__device__ float g_scores[BATCH * CH];
__device__ int   g_idx[BATCH * KSEL];

// ---------------------------------------------------------------------------
// Kernel 1: per-(b,c) plane curvature score = sum |valid 3x3 xcorr response|
// ONE WARP per plane, straight from global (no smem).
// R16: 64-thread blocks (2 warps) -> 8192 blocks, ~21 resident/SM: finer
// scheduling quanta to lift achieved occupancy (R15: 53.8% achieved vs 62.5%
// cap at 128-thr/10-block config). Body identical to the R15 passing config:
//  - lane l loads float2 at cols (2l,2l+1) per row (LDG.64, each byte once)
//  - 8-deep register prefetch queue q[i&7] (consume row i+2, load row i+10)
//  - symmetric-stencil factorization: conv = wc*(tA+tC)+we*(mA+mC+tB)+w4*mB
//  - branchless; lane 31's Kahan state zeroed pre-reduce
//  - loop split: prefetch i<54 (last load i=53 -> row 63), drain i=54..61
//  - NUMERICS: fp32 Kahan in-loop + fp64 final warp reduce ONLY (R14 lesson:
//    fp64 in any hot loop is ~1 op/cyc/SM on sm_103a — never again).
// ---------------------------------------------------------------------------
__global__ __launch_bounds__(64) void score_kernel(const float* __restrict__ x,
                                                   const float* __restrict__ wgt) {
    const int lane  = threadIdx.x & 31;
    const int warp  = threadIdx.x >> 5;
    const int plane = blockIdx.x * 2 + warp;

    const float wc = __ldg(wgt + 0);   // corners (-1/16)
    const float we = __ldg(wgt + 1);   // edges   ( 5/16)
    const float w4 = __ldg(wgt + 4);   // center  (-1)

    const float2* b2 = reinterpret_cast<const float2*>(x)
                       + (size_t)plane * (PLANE / 2) + lane;
    const unsigned FULL = 0xffffffffu;

    // prologue: rows 0,1 -> factored state; rows 2..9 -> prefetch queue
    const float2 r0 = b2[0 * 32];
    const float2 r1 = b2[1 * 32];
    float2 q[8];
    #pragma unroll
    for (int j = 0; j < 8; ++j) q[j] = b2[(j + 2) * 32];

    const float r0nx = __shfl_down_sync(FULL, r0.x, 1);
    const float r0ny = __shfl_down_sync(FULL, r0.y, 1);
    const float r1nx = __shfl_down_sync(FULL, r1.x, 1);
    const float r1ny = __shfl_down_sync(FULL, r1.y, 1);

    float tA0 = r0.x + r0nx, tA1 = r0.y + r0ny;
    float mA0 = r0.y,        mA1 = r0nx;
    float tB0 = r1.x + r1nx, tB1 = r1.y + r1ny;
    float mB0 = r1.y,        mB1 = r1nx;

    float sum  = 0.0f;   // Kahan accumulator
    float comp = 0.0f;   // Kahan compensation

    auto body = [&](const float2 c) {
        const float cnx = __shfl_down_sync(FULL, c.x, 1);
        const float cny = __shfl_down_sync(FULL, c.y, 1);
        const float tC0 = c.x + cnx, tC1 = c.y + cny;
        const float mC0 = c.y,       mC1 = cnx;

        const float u0 = tA0 + tC0;
        float v0 = mA0 + mC0;
        v0 += tB0;
        float conv0 = wc * u0;
        conv0 = fmaf(we, v0, conv0);
        conv0 = fmaf(w4, mB0, conv0);

        const float u1 = tA1 + tC1;
        float v1 = mA1 + mC1;
        v1 += tB1;
        float conv1 = wc * u1;
        conv1 = fmaf(we, v1, conv1);
        conv1 = fmaf(w4, mB1, conv1);

        const float rowsum = fabsf(conv0) + fabsf(conv1);
        const float y = __fadd_rn(rowsum, -comp);
        const float t = __fadd_rn(sum, y);
        comp = __fadd_rn(__fadd_rn(t, -sum), -y);
        sum = t;

        tA0 = tB0; tA1 = tB1; mA0 = mB0; mA1 = mB1;
        tB0 = tC0; tB1 = tC1; mB0 = mC0; mB1 = mC1;
    };

    #pragma unroll 8
    for (int i = 0; i < 54; ++i) {
        const float2 c = q[i & 7];
        q[i & 7] = b2[(i + 10) * 32];
        body(c);
    }
    #pragma unroll
    for (int i = 54; i < HH - 2; ++i) {
        body(q[i & 7]);
    }

    if (lane == 31) { sum = 0.0f; comp = 0.0f; }

    double acc = (double)sum - (double)comp;
    #pragma unroll
    for (int off = 16; off > 0; off >>= 1)
        acc += __shfl_xor_sync(FULL, acc, off);
    if (lane == 0) g_scores[plane] = (float)acc;
}

// ---------------------------------------------------------------------------
// Kernel 2: per-batch top-k (k=256) via exact rank counting in FP32
// (lax.top_k order: descending value, ties -> lower index).
// ---------------------------------------------------------------------------
__global__ __launch_bounds__(512) void topk_kernel() {
    __shared__ float s[CH];
    const int b   = blockIdx.x;
    const int tid = threadIdx.x;

    s[tid] = g_scores[b * CH + tid];
    __syncthreads();

    const float my = s[tid];
    int rank = 0;
    #pragma unroll 8
    for (int j = 0; j < CH; ++j) {
        const float v = s[j];
        rank += (v > my) || (v == my && j < tid);
    }
    if (rank < KSEL) g_idx[b * KSEL + rank] = tid;
}

// ---------------------------------------------------------------------------
// Kernel 3: gather selected channel planes. 128 thr x 8 independent float4
// copies. Reversed batch traversal (R15 win): score streamed batches 0..31,
// so L2 holds the tail; consuming it first converts those reads to L2 hits.
// Reads default-cached on purpose; writes streaming (__stcs, zero reuse).
// ---------------------------------------------------------------------------
__global__ __launch_bounds__(128) void gather_kernel(const float* __restrict__ x,
                                                     float* __restrict__ out) {
    const int b = (BATCH - 1) - blockIdx.y;      // reverse order
    const int r = blockIdx.x;
    const int c = __ldg(&g_idx[b * KSEL + r]);   // broadcast

    const float4* __restrict__ src = reinterpret_cast<const float4*>(x)
                        + ((size_t)(b * CH + c)) * (PLANE / 4);
    float4* __restrict__ dst = reinterpret_cast<float4*>(out)
                  + ((size_t)(b * KSEL + r)) * (PLANE / 4);
    const int tid = threadIdx.x;

    float4 v0 = src[tid + 0 * 128];
    float4 v1 = src[tid + 1 * 128];
    float4 v2 = src[tid + 2 * 128];
    float4 v3 = src[tid + 3 * 128];
    float4 v4 = src[tid + 4 * 128];
    float4 v5 = src[tid + 5 * 128];
    float4 v6 = src[tid + 6 * 128];
    float4 v7 = src[tid + 7 * 128];
    __stcs(&dst[tid + 0 * 128], v0);
    __stcs(&dst[tid + 1 * 128], v1);
    __stcs(&dst[tid + 2 * 128], v2);
    __stcs(&dst[tid + 3 * 128], v3);
    __stcs(&dst[tid + 4 * 128], v4);
    __stcs(&dst[tid + 5 * 128], v5);
    __stcs(&dst[tid + 6 * 128], v6);
    __stcs(&dst[tid + 7 * 128], v7);
}

// ---------------------------------------------------------------------------
// Single stream, 3 launches (R12-R14: forks/chunking net-lose on this chip).
// ---------------------------------------------------------------------------
extern "C" void kernel_launch(void* const* d_in, const int* in_sizes, int n_in,
                              void* d_out, int out_size) {
    const float* x = (const float*)d_in[0];
    const float* w = (const float*)d_in[1];
    if (n_in >= 2 && in_sizes[0] == 9) {   // defensive input-order check
        const float* t = x; x = w; w = t;
    }
    float* out = (float*)d_out;

    score_kernel<<<(BATCH * CH) / 2, 64>>>(x, w);
    topk_kernel<<<BATCH, 512>>>();
    gather_kernel<<<dim3(KSEL, BATCH), 128>>>(x, out);
}